// round 1
// baseline (speedup 1.0000x reference)
#include <cuda_runtime.h>
#include <math.h>

#define N_NODES 50000
#define N_EDGES 800000
#define F 64          // F_IN == F_HID
#define NOUT 128      // z-cols (64) | h-cols (64)
#define KTOT 192      // x | tx1 | y

// ---------------- device scratch (allocation-free) ----------------
__device__ float g_deg[N_NODES];
__device__ float g_dis[N_NODES];
__device__ int   g_count[N_NODES];
__device__ int   g_rowptr[N_NODES + 1];
__device__ int   g_cursor[N_NODES];
__device__ int   g_src[N_EDGES];
__device__ float g_nrm[N_EDGES];
__device__ float g_tx1[N_NODES * F];
__device__ float g_y[N_NODES * F];
__device__ float g_C[N_NODES * NOUT];
__device__ float g_Wc[KTOT * NOUT];
__device__ float g_bz[F];
__device__ float g_bh[F];

// ---------------- kernels ----------------

__global__ void init_kernel(int n) {
    int i = blockIdx.x * blockDim.x + threadIdx.x;
    if (i < n) { g_deg[i] = 0.0f; g_count[i] = 0; }
}

// deg[row] += w ; count[col] += 1
__global__ void edge_pass1_kernel(const int* __restrict__ ei,
                                  const float* __restrict__ ew, int E) {
    int e = blockIdx.x * blockDim.x + threadIdx.x;
    if (e >= E) return;
    atomicAdd(&g_deg[ei[e]], ew[e]);
    atomicAdd(&g_count[ei[E + e]], 1);
}

__global__ void dis_kernel(int n) {
    int i = blockIdx.x * blockDim.x + threadIdx.x;
    if (i >= n) return;
    float d = g_deg[i];
    g_dis[i] = (d > 0.0f) ? rsqrtf(d) : 0.0f;
}

// single-block exclusive scan of g_count -> g_rowptr / g_cursor
__global__ void scan_kernel(int n) {
    __shared__ int warp_sums[32];
    __shared__ int s_carry;
    __shared__ int s_total;
    int tid = threadIdx.x, lane = tid & 31, wid = tid >> 5;
    if (tid == 0) s_carry = 0;
    __syncthreads();
    for (int base = 0; base < n; base += 1024) {
        int i = base + tid;
        int v = (i < n) ? g_count[i] : 0;
        int incl = v;
        #pragma unroll
        for (int o = 1; o < 32; o <<= 1) {
            int t = __shfl_up_sync(0xffffffffu, incl, o);
            if (lane >= o) incl += t;
        }
        if (lane == 31) warp_sums[wid] = incl;
        __syncthreads();
        if (wid == 0) {
            int s = warp_sums[lane];
            int sincl = s;
            #pragma unroll
            for (int o = 1; o < 32; o <<= 1) {
                int t = __shfl_up_sync(0xffffffffu, sincl, o);
                if (lane >= o) sincl += t;
            }
            warp_sums[lane] = sincl - s;  // exclusive over warps
            if (lane == 31) s_total = sincl;
        }
        __syncthreads();
        int carry = s_carry;
        int excl = carry + warp_sums[wid] + incl - v;
        if (i < n) { g_rowptr[i] = excl; g_cursor[i] = excl; }
        __syncthreads();
        if (tid == 0) s_carry = carry + s_total;
        __syncthreads();
    }
    if (tid == 0) g_rowptr[n] = s_carry;
}

// norm + scatter edges into col-keyed CSR
__global__ void scatter_kernel(const int* __restrict__ ei,
                               const float* __restrict__ ew, int E) {
    int e = blockIdx.x * blockDim.x + threadIdx.x;
    if (e >= E) return;
    int r = ei[e], c = ei[E + e];
    float nrm = -g_dis[r] * ew[e] * g_dis[c];
    int p = atomicAdd(&g_cursor[c], 1);
    g_src[p] = r;
    g_nrm[p] = nrm;
}

// warp-per-node gather propagation: dst[i] = sum_in norm * feat[src]
__global__ void prop_kernel(const float* __restrict__ xin, int pass, int n) {
    int warp = (blockIdx.x * blockDim.x + threadIdx.x) >> 5;
    int lane = threadIdx.x & 31;
    if (warp >= n) return;
    const float* __restrict__ feat = pass ? g_tx1 : xin;
    float* __restrict__ dst = pass ? g_y : g_tx1;
    int s = g_rowptr[warp], e = g_rowptr[warp + 1];
    float a0 = 0.0f, a1 = 0.0f;
    for (int p = s; p < e; p++) {
        int src = __ldg(&g_src[p]);
        float w = __ldg(&g_nrm[p]);
        a0 += w * __ldg(&feat[src * F + lane]);
        a1 += w * __ldg(&feat[src * F + 32 + lane]);
    }
    dst[warp * F + lane] = a0;
    dst[warp * F + 32 + lane] = a1;
}

// build combined weights (192 x 128) and biases
__global__ void weights_kernel(const float* __restrict__ Wxz,
                               const float* __restrict__ bxz,
                               const float* __restrict__ bhz,
                               const float* __restrict__ Wxh,
                               const float* __restrict__ bxh,
                               const float* __restrict__ bhh) {
    for (int idx = threadIdx.x; idx < KTOT * NOUT; idx += blockDim.x) {
        int r = idx / NOUT, c = idx % NOUT;
        int seg = r / 64, i = r % 64;
        const float* W = (c < 64) ? Wxz : Wxh;
        int j = (c < 64) ? c : (c - 64);
        float v;
        if (seg == 0)      v = W[(0 * 64 + i) * 64 + j] - W[(2 * 64 + i) * 64 + j];
        else if (seg == 1) v = W[(1 * 64 + i) * 64 + j];
        else               v = 2.0f * W[(2 * 64 + i) * 64 + j];
        g_Wc[idx] = v;
    }
    if (threadIdx.x < F) {
        g_bz[threadIdx.x] = bxz[threadIdx.x] + bhz[threadIdx.x];
        g_bh[threadIdx.x] = bxh[threadIdx.x] + bhh[threadIdx.x];
    }
}

// C[n x 128] = [x | tx1 | y] (n x 192) @ g_Wc (192 x 128)
#define BM 128
#define BN 128
#define BK 16
__global__ __launch_bounds__(256, 2)
void gemm_kernel(const float* __restrict__ x, int n) {
    __shared__ float As[BM * (BK + 1)];
    __shared__ float Bs[BK * BN];
    int tid = threadIdx.x;
    int tx = tid & 15, ty = tid >> 4;
    int row0 = blockIdx.x * BM;
    float acc[8][8];
    #pragma unroll
    for (int i = 0; i < 8; i++)
        #pragma unroll
        for (int j = 0; j < 8; j++) acc[i][j] = 0.0f;

    for (int seg = 0; seg < 3; seg++) {
        const float* __restrict__ feat = (seg == 0) ? x : ((seg == 1) ? g_tx1 : g_y);
        const float* __restrict__ wseg = g_Wc + seg * 64 * NOUT;
        for (int kk = 0; kk < 64; kk += BK) {
            #pragma unroll
            for (int it = 0; it < 8; it++) {
                int e = tid + it * 256;
                int k = e & 15, i = e >> 4;
                int r = row0 + i;
                As[i * (BK + 1) + k] = (r < n) ? feat[r * F + kk + k] : 0.0f;
            }
            #pragma unroll
            for (int it = 0; it < 8; it++) {
                int e = tid + it * 256;
                int j = e & 127, k = e >> 7;
                Bs[k * BN + j] = wseg[(kk + k) * NOUT + j];
            }
            __syncthreads();
            #pragma unroll
            for (int k = 0; k < BK; k++) {
                float a[8], b[8];
                #pragma unroll
                for (int i = 0; i < 8; i++) a[i] = As[(ty * 8 + i) * (BK + 1) + k];
                #pragma unroll
                for (int j = 0; j < 8; j++) b[j] = Bs[k * BN + tx * 8 + j];
                #pragma unroll
                for (int i = 0; i < 8; i++)
                    #pragma unroll
                    for (int j = 0; j < 8; j++) acc[i][j] += a[i] * b[j];
            }
            __syncthreads();
        }
    }
    #pragma unroll
    for (int i = 0; i < 8; i++) {
        int r = row0 + ty * 8 + i;
        if (r < n) {
            #pragma unroll
            for (int j = 0; j < 8; j++)
                g_C[r * NOUT + tx * 8 + j] = acc[i][j];
        }
    }
}

__device__ __forceinline__ float sigm(float v) { return 1.0f / (1.0f + expf(-v)); }

// warp-per-node: gates + GRU combine + tanh + 64->2 head + sigmoid
__global__ void final_kernel(const float* __restrict__ Wlin,
                             const float* __restrict__ blin,
                             float* __restrict__ out, int n) {
    int warp = (blockIdx.x * blockDim.x + threadIdx.x) >> 5;
    int lane = threadIdx.x & 31;
    if (warp >= n) return;
    const float* c = g_C + warp * NOUT;
    float az0 = c[lane], az1 = c[lane + 32];
    float ah0 = c[lane + 64], ah1 = c[lane + 96];
    float z0 = sigm(az0 + g_bz[lane]);
    float z1 = sigm(az1 + g_bz[lane + 32]);
    float t0 = tanhf(ah0 + g_bh[lane]);
    float t1 = tanhf(ah1 + g_bh[lane + 32]);
    float u0 = tanhf((1.0f - z0) * t0);
    float u1 = tanhf((1.0f - z1) * t1);
    float s0 = u0 * __ldg(&Wlin[lane * 2 + 0]) + u1 * __ldg(&Wlin[(lane + 32) * 2 + 0]);
    float s1 = u0 * __ldg(&Wlin[lane * 2 + 1]) + u1 * __ldg(&Wlin[(lane + 32) * 2 + 1]);
    #pragma unroll
    for (int o = 16; o > 0; o >>= 1) {
        s0 += __shfl_down_sync(0xffffffffu, s0, o);
        s1 += __shfl_down_sync(0xffffffffu, s1, o);
    }
    if (lane == 0) {
        out[warp * 2 + 0] = sigm(s0 + blin[0]);
        out[warp * 2 + 1] = sigm(s1 + blin[1]);
    }
}

// ---------------- launch ----------------
extern "C" void kernel_launch(void* const* d_in, const int* in_sizes, int n_in,
                              void* d_out, int out_size) {
    const float* x   = (const float*)d_in[0];
    const int*   ei  = (const int*)d_in[1];
    const float* ew  = (const float*)d_in[2];
    const float* Wxz = (const float*)d_in[3];
    const float* bxz = (const float*)d_in[4];
    const float* bhz = (const float*)d_in[6];
    const float* Wxh = (const float*)d_in[11];
    const float* bxh = (const float*)d_in[12];
    const float* bhh = (const float*)d_in[14];
    const float* Wlin = (const float*)d_in[15];
    const float* blin = (const float*)d_in[16];
    float* out = (float*)d_out;

    int n = in_sizes[0] / F;       // 50000
    int E = in_sizes[2];           // 800000

    init_kernel<<<(n + 255) / 256, 256>>>(n);
    edge_pass1_kernel<<<(E + 255) / 256, 256>>>(ei, ew, E);
    dis_kernel<<<(n + 255) / 256, 256>>>(n);
    scan_kernel<<<1, 1024>>>(n);
    scatter_kernel<<<(E + 255) / 256, 256>>>(ei, ew, E);

    // tx1 = Lhat x ; y = Lhat tx1
    int prop_blocks = (n * 32 + 255) / 256;
    prop_kernel<<<prop_blocks, 256>>>(x, 0, n);
    prop_kernel<<<prop_blocks, 256>>>(x, 1, n);

    weights_kernel<<<1, 256>>>(Wxz, bxz, bhz, Wxh, bxh, bhh);
    gemm_kernel<<<(n + BM - 1) / BM, 256>>>(x, n);
    final_kernel<<<(n * 32 + 255) / 256, 256>>>(Wlin, blin, out, n);
    (void)n_in; (void)out_size;
}

// round 2
// speedup vs baseline: 1.1007x; 1.1007x over previous
#include <cuda_runtime.h>
#include <math.h>

#define N_NODES 50000
#define N_EDGES 800000
#define F 64          // F_IN == F_HID
#define NOUT 128      // z-cols (64) | h-cols (64)
#define KTOT 192      // x | tx1 | y
#define SCAN_TILE 1024
#define MAX_BLOCKS ((N_NODES + SCAN_TILE - 1) / SCAN_TILE + 1)

// ---------------- device scratch (allocation-free) ----------------
__device__ float g_deg[N_NODES];
__device__ float g_dis[N_NODES];
__device__ int   g_count[N_NODES];
__device__ int   g_rowptr[N_NODES + 1];
__device__ int   g_cursor[N_NODES];
__device__ int   g_bsum[MAX_BLOCKS];
__device__ int   g_boff[MAX_BLOCKS];
__device__ int   g_src[N_EDGES];
__device__ float g_nrm[N_EDGES];
__device__ float g_tx1[N_NODES * F];
__device__ float g_y[N_NODES * F];
__device__ float g_C[N_NODES * NOUT];
__device__ float g_Wc[KTOT * NOUT];
__device__ float g_bz[F];
__device__ float g_bh[F];

// ---------------- kernels ----------------

__global__ void init_kernel(int n) {
    int i = blockIdx.x * blockDim.x + threadIdx.x;
    if (i < n) { g_deg[i] = 0.0f; g_count[i] = 0; }
}

// deg[row] += w ; count[col] += 1
__global__ void edge_pass1_kernel(const int* __restrict__ ei,
                                  const float* __restrict__ ew, int E) {
    int e = blockIdx.x * blockDim.x + threadIdx.x;
    if (e >= E) return;
    atomicAdd(&g_deg[ei[e]], ew[e]);
    atomicAdd(&g_count[ei[E + e]], 1);
}

__global__ void dis_kernel(int n) {
    int i = blockIdx.x * blockDim.x + threadIdx.x;
    if (i >= n) return;
    float d = g_deg[i];
    g_dis[i] = (d > 0.0f) ? rsqrtf(d) : 0.0f;
}

// ---- 3-phase grid-wide exclusive scan of g_count -> g_rowptr/g_cursor ----

// Phase 1: per-block (1024-element) local exclusive scan; block total -> g_bsum
__global__ void scan_phase1_kernel(int n) {
    __shared__ int warp_sums[32];
    int tid = threadIdx.x, lane = tid & 31, wid = tid >> 5;
    int i = blockIdx.x * SCAN_TILE + tid;
    int v = (i < n) ? g_count[i] : 0;
    int incl = v;
    #pragma unroll
    for (int o = 1; o < 32; o <<= 1) {
        int t = __shfl_up_sync(0xffffffffu, incl, o);
        if (lane >= o) incl += t;
    }
    if (lane == 31) warp_sums[wid] = incl;
    __syncthreads();
    if (wid == 0) {
        int s = warp_sums[lane];
        int sincl = s;
        #pragma unroll
        for (int o = 1; o < 32; o <<= 1) {
            int t = __shfl_up_sync(0xffffffffu, sincl, o);
            if (lane >= o) sincl += t;
        }
        warp_sums[lane] = sincl - s;  // exclusive over warps
        if (lane == 31) g_bsum[blockIdx.x] = sincl;
    }
    __syncthreads();
    int excl = warp_sums[wid] + incl - v;  // local exclusive
    if (i < n) g_rowptr[i] = excl;
}

// Phase 2: one warp scans the block sums (nb <= 49)
__global__ void scan_phase2_kernel(int nb, int n) {
    int lane = threadIdx.x;
    int carry = 0;
    for (int base = 0; base < nb; base += 32) {
        int idx = base + lane;
        int v = (idx < nb) ? g_bsum[idx] : 0;
        int incl = v;
        #pragma unroll
        for (int o = 1; o < 32; o <<= 1) {
            int t = __shfl_up_sync(0xffffffffu, incl, o);
            if (lane >= o) incl += t;
        }
        if (idx < nb) g_boff[idx] = carry + incl - v;
        carry += __shfl_sync(0xffffffffu, incl, 31);
    }
    if (lane == 0) g_rowptr[n] = carry;
}

// Phase 3: add block offsets; also populate cursor
__global__ void scan_phase3_kernel(int n) {
    int i = blockIdx.x * blockDim.x + threadIdx.x;
    if (i >= n) return;
    int val = g_rowptr[i] + g_boff[i >> 10];
    g_rowptr[i] = val;
    g_cursor[i] = val;
}

// norm + scatter edges into col-keyed CSR
__global__ void scatter_kernel(const int* __restrict__ ei,
                               const float* __restrict__ ew, int E) {
    int e = blockIdx.x * blockDim.x + threadIdx.x;
    if (e >= E) return;
    int r = ei[e], c = ei[E + e];
    float nrm = -g_dis[r] * ew[e] * g_dis[c];
    int p = atomicAdd(&g_cursor[c], 1);
    g_src[p] = r;
    g_nrm[p] = nrm;
}

// warp-per-node gather propagation: dst[i] = sum_in norm * feat[src]
__global__ void prop_kernel(const float* __restrict__ xin, int pass, int n) {
    int warp = (blockIdx.x * blockDim.x + threadIdx.x) >> 5;
    int lane = threadIdx.x & 31;
    if (warp >= n) return;
    const float* __restrict__ feat = pass ? g_tx1 : xin;
    float* __restrict__ dst = pass ? g_y : g_tx1;
    int s = g_rowptr[warp], e = g_rowptr[warp + 1];
    float a0 = 0.0f, a1 = 0.0f;
    int p = s;
    for (; p + 1 < e; p += 2) {
        int s0 = __ldg(&g_src[p]);
        int s1 = __ldg(&g_src[p + 1]);
        float w0 = __ldg(&g_nrm[p]);
        float w1 = __ldg(&g_nrm[p + 1]);
        a0 += w0 * __ldg(&feat[s0 * F + lane]);
        a1 += w0 * __ldg(&feat[s0 * F + 32 + lane]);
        a0 += w1 * __ldg(&feat[s1 * F + lane]);
        a1 += w1 * __ldg(&feat[s1 * F + 32 + lane]);
    }
    if (p < e) {
        int s0 = __ldg(&g_src[p]);
        float w0 = __ldg(&g_nrm[p]);
        a0 += w0 * __ldg(&feat[s0 * F + lane]);
        a1 += w0 * __ldg(&feat[s0 * F + 32 + lane]);
    }
    dst[warp * F + lane] = a0;
    dst[warp * F + 32 + lane] = a1;
}

// build combined weights (192 x 128) and biases
__global__ void weights_kernel(const float* __restrict__ Wxz,
                               const float* __restrict__ bxz,
                               const float* __restrict__ bhz,
                               const float* __restrict__ Wxh,
                               const float* __restrict__ bxh,
                               const float* __restrict__ bhh) {
    for (int idx = threadIdx.x; idx < KTOT * NOUT; idx += blockDim.x) {
        int r = idx / NOUT, c = idx % NOUT;
        int seg = r / 64, i = r % 64;
        const float* W = (c < 64) ? Wxz : Wxh;
        int j = (c < 64) ? c : (c - 64);
        float v;
        if (seg == 0)      v = W[(0 * 64 + i) * 64 + j] - W[(2 * 64 + i) * 64 + j];
        else if (seg == 1) v = W[(1 * 64 + i) * 64 + j];
        else               v = 2.0f * W[(2 * 64 + i) * 64 + j];
        g_Wc[idx] = v;
    }
    if (threadIdx.x < F) {
        g_bz[threadIdx.x] = bxz[threadIdx.x] + bhz[threadIdx.x];
        g_bh[threadIdx.x] = bxh[threadIdx.x] + bhh[threadIdx.x];
    }
}

// C[n x 128] = [x | tx1 | y] (n x 192) @ g_Wc (192 x 128)
#define BM 128
#define BN 128
#define BK 16
__global__ __launch_bounds__(256, 2)
void gemm_kernel(const float* __restrict__ x, int n) {
    __shared__ float As[BM * (BK + 1)];
    __shared__ float Bs[BK * BN];
    int tid = threadIdx.x;
    int tx = tid & 15, ty = tid >> 4;
    int row0 = blockIdx.x * BM;
    float acc[8][8];
    #pragma unroll
    for (int i = 0; i < 8; i++)
        #pragma unroll
        for (int j = 0; j < 8; j++) acc[i][j] = 0.0f;

    for (int seg = 0; seg < 3; seg++) {
        const float* __restrict__ feat = (seg == 0) ? x : ((seg == 1) ? g_tx1 : g_y);
        const float* __restrict__ wseg = g_Wc + seg * 64 * NOUT;
        for (int kk = 0; kk < 64; kk += BK) {
            #pragma unroll
            for (int it = 0; it < 8; it++) {
                int e = tid + it * 256;
                int k = e & 15, i = e >> 4;
                int r = row0 + i;
                As[i * (BK + 1) + k] = (r < n) ? feat[r * F + kk + k] : 0.0f;
            }
            #pragma unroll
            for (int it = 0; it < 8; it++) {
                int e = tid + it * 256;
                int j = e & 127, k = e >> 7;
                Bs[k * BN + j] = wseg[(kk + k) * NOUT + j];
            }
            __syncthreads();
            #pragma unroll
            for (int k = 0; k < BK; k++) {
                float a[8], b[8];
                #pragma unroll
                for (int i = 0; i < 8; i++) a[i] = As[(ty * 8 + i) * (BK + 1) + k];
                #pragma unroll
                for (int j = 0; j < 8; j++) b[j] = Bs[k * BN + tx * 8 + j];
                #pragma unroll
                for (int i = 0; i < 8; i++)
                    #pragma unroll
                    for (int j = 0; j < 8; j++) acc[i][j] += a[i] * b[j];
            }
            __syncthreads();
        }
    }
    #pragma unroll
    for (int i = 0; i < 8; i++) {
        int r = row0 + ty * 8 + i;
        if (r < n) {
            #pragma unroll
            for (int j = 0; j < 8; j++)
                g_C[r * NOUT + tx * 8 + j] = acc[i][j];
        }
    }
}

__device__ __forceinline__ float sigm(float v) { return 1.0f / (1.0f + expf(-v)); }

// warp-per-node: gates + GRU combine + tanh + 64->2 head + sigmoid
__global__ void final_kernel(const float* __restrict__ Wlin,
                             const float* __restrict__ blin,
                             float* __restrict__ out, int n) {
    int warp = (blockIdx.x * blockDim.x + threadIdx.x) >> 5;
    int lane = threadIdx.x & 31;
    if (warp >= n) return;
    const float* c = g_C + warp * NOUT;
    float az0 = c[lane], az1 = c[lane + 32];
    float ah0 = c[lane + 64], ah1 = c[lane + 96];
    float z0 = sigm(az0 + g_bz[lane]);
    float z1 = sigm(az1 + g_bz[lane + 32]);
    float t0 = tanhf(ah0 + g_bh[lane]);
    float t1 = tanhf(ah1 + g_bh[lane + 32]);
    float u0 = tanhf((1.0f - z0) * t0);
    float u1 = tanhf((1.0f - z1) * t1);
    float s0 = u0 * __ldg(&Wlin[lane * 2 + 0]) + u1 * __ldg(&Wlin[(lane + 32) * 2 + 0]);
    float s1 = u0 * __ldg(&Wlin[lane * 2 + 1]) + u1 * __ldg(&Wlin[(lane + 32) * 2 + 1]);
    #pragma unroll
    for (int o = 16; o > 0; o >>= 1) {
        s0 += __shfl_down_sync(0xffffffffu, s0, o);
        s1 += __shfl_down_sync(0xffffffffu, s1, o);
    }
    if (lane == 0) {
        out[warp * 2 + 0] = sigm(s0 + blin[0]);
        out[warp * 2 + 1] = sigm(s1 + blin[1]);
    }
}

// ---------------- launch ----------------
extern "C" void kernel_launch(void* const* d_in, const int* in_sizes, int n_in,
                              void* d_out, int out_size) {
    const float* x   = (const float*)d_in[0];
    const int*   ei  = (const int*)d_in[1];
    const float* ew  = (const float*)d_in[2];
    const float* Wxz = (const float*)d_in[3];
    const float* bxz = (const float*)d_in[4];
    const float* bhz = (const float*)d_in[6];
    const float* Wxh = (const float*)d_in[11];
    const float* bxh = (const float*)d_in[12];
    const float* bhh = (const float*)d_in[14];
    const float* Wlin = (const float*)d_in[15];
    const float* blin = (const float*)d_in[16];
    float* out = (float*)d_out;

    int n = in_sizes[0] / F;       // 50000
    int E = in_sizes[2];           // 800000
    int nb = (n + SCAN_TILE - 1) / SCAN_TILE;

    init_kernel<<<(n + 255) / 256, 256>>>(n);
    edge_pass1_kernel<<<(E + 255) / 256, 256>>>(ei, ew, E);
    dis_kernel<<<(n + 255) / 256, 256>>>(n);
    scan_phase1_kernel<<<nb, SCAN_TILE>>>(n);
    scan_phase2_kernel<<<1, 32>>>(nb, n);
    scan_phase3_kernel<<<(n + 255) / 256, 256>>>(n);
    scatter_kernel<<<(E + 255) / 256, 256>>>(ei, ew, E);

    // tx1 = Lhat x ; y = Lhat tx1
    int prop_blocks = (n * 32 + 255) / 256;
    prop_kernel<<<prop_blocks, 256>>>(x, 0, n);
    prop_kernel<<<prop_blocks, 256>>>(x, 1, n);

    weights_kernel<<<1, 256>>>(Wxz, bxz, bhz, Wxh, bxh, bhh);
    gemm_kernel<<<(n + BM - 1) / BM, 256>>>(x, n);
    final_kernel<<<(n * 32 + 255) / 256, 256>>>(Wlin, blin, out, n);
    (void)n_in; (void)out_size;
}

// round 5
// speedup vs baseline: 1.4769x; 1.3417x over previous
#include <cuda_runtime.h>
#include <cuda_bf16.h>
#include <cstdint>
#include <math.h>

#define N_NODES 50000
#define N_EDGES 800000
#define F 64          // F_IN == F_HID
#define KTOT 192      // x | tx1 | y
#define NOUT 128      // z (64) | h (64)
#define SCAN_TILE 1024
#define MAX_BLOCKS ((N_NODES + SCAN_TILE - 1) / SCAN_TILE + 1)

// ---------------- device scratch (allocation-free) ----------------
__device__ float g_deg[N_NODES];
__device__ float g_dis[N_NODES];
__device__ int   g_count[N_NODES];
__device__ int   g_rowptr[N_NODES + 1];
__device__ int   g_cursor[N_NODES];
__device__ int   g_bsum[MAX_BLOCKS];
__device__ int   g_boff[MAX_BLOCKS];
__device__ int   g_src[N_EDGES];
__device__ float g_nrm[N_EDGES];
__device__ float g_tx1[N_NODES * F];
__device__ __align__(16) __nv_bfloat16 g_Ahi[N_NODES * KTOT];
__device__ __align__(16) __nv_bfloat16 g_Alo[N_NODES * KTOT];
__device__ __align__(16) __nv_bfloat16 g_Bhi[NOUT * KTOT];   // [n][k], k-contiguous
__device__ __align__(16) __nv_bfloat16 g_Blo[NOUT * KTOT];
__device__ float g_bz[F];
__device__ float g_bh[F];

// ---------------- PTX helpers ----------------
__device__ __forceinline__ uint32_t smem_u32(const void* p) {
    uint32_t a;
    asm("{ .reg .u64 t; cvta.to.shared.u64 t, %1; cvt.u32.u64 %0, t; }" : "=r"(a) : "l"(p));
    return a;
}
__device__ __forceinline__ void ldsm4(uint32_t (&d)[4], uint32_t addr) {
    asm volatile("ldmatrix.sync.aligned.m8n8.x4.shared.b16 {%0,%1,%2,%3}, [%4];\n"
                 : "=r"(d[0]), "=r"(d[1]), "=r"(d[2]), "=r"(d[3]) : "r"(addr));
}
__device__ __forceinline__ void mma_bf16(float (&c)[4], const uint32_t (&a)[4],
                                         uint32_t b0, uint32_t b1) {
    asm volatile(
        "mma.sync.aligned.m16n8k16.row.col.f32.bf16.bf16.f32 "
        "{%0,%1,%2,%3}, {%4,%5,%6,%7}, {%8,%9}, {%0,%1,%2,%3};\n"
        : "+f"(c[0]), "+f"(c[1]), "+f"(c[2]), "+f"(c[3])
        : "r"(a[0]), "r"(a[1]), "r"(a[2]), "r"(a[3]), "r"(b0), "r"(b1));
}

// ---------------- kernels ----------------

__global__ void init_kernel(int n) {
    int i = blockIdx.x * blockDim.x + threadIdx.x;
    if (i < n) { g_deg[i] = 0.0f; g_count[i] = 0; }
}

__global__ void edge_pass1_kernel(const int* __restrict__ ei,
                                  const float* __restrict__ ew, int E) {
    int e = blockIdx.x * blockDim.x + threadIdx.x;
    if (e >= E) return;
    atomicAdd(&g_deg[ei[e]], ew[e]);
    atomicAdd(&g_count[ei[E + e]], 1);
}

__global__ void dis_kernel(int n) {
    int i = blockIdx.x * blockDim.x + threadIdx.x;
    if (i >= n) return;
    float d = g_deg[i];
    g_dis[i] = (d > 0.0f) ? rsqrtf(d) : 0.0f;
}

__global__ void scan_phase1_kernel(int n) {
    __shared__ int warp_sums[32];
    int tid = threadIdx.x, lane = tid & 31, wid = tid >> 5;
    int i = blockIdx.x * SCAN_TILE + tid;
    int v = (i < n) ? g_count[i] : 0;
    int incl = v;
    #pragma unroll
    for (int o = 1; o < 32; o <<= 1) {
        int t = __shfl_up_sync(0xffffffffu, incl, o);
        if (lane >= o) incl += t;
    }
    if (lane == 31) warp_sums[wid] = incl;
    __syncthreads();
    if (wid == 0) {
        int s = warp_sums[lane];
        int sincl = s;
        #pragma unroll
        for (int o = 1; o < 32; o <<= 1) {
            int t = __shfl_up_sync(0xffffffffu, sincl, o);
            if (lane >= o) sincl += t;
        }
        warp_sums[lane] = sincl - s;
        if (lane == 31) g_bsum[blockIdx.x] = sincl;
    }
    __syncthreads();
    int excl = warp_sums[wid] + incl - v;
    if (i < n) g_rowptr[i] = excl;
}

__global__ void scan_phase2_kernel(int nb, int n) {
    int lane = threadIdx.x;
    int carry = 0;
    for (int base = 0; base < nb; base += 32) {
        int idx = base + lane;
        int v = (idx < nb) ? g_bsum[idx] : 0;
        int incl = v;
        #pragma unroll
        for (int o = 1; o < 32; o <<= 1) {
            int t = __shfl_up_sync(0xffffffffu, incl, o);
            if (lane >= o) incl += t;
        }
        if (idx < nb) g_boff[idx] = carry + incl - v;
        carry += __shfl_sync(0xffffffffu, incl, 31);
    }
    if (lane == 0) g_rowptr[n] = carry;
}

__global__ void scan_phase3_kernel(int n) {
    int i = blockIdx.x * blockDim.x + threadIdx.x;
    if (i >= n) return;
    int val = g_rowptr[i] + g_boff[i >> 10];
    g_rowptr[i] = val;
    g_cursor[i] = val;
}

__global__ void scatter_kernel(const int* __restrict__ ei,
                               const float* __restrict__ ew, int E) {
    int e = blockIdx.x * blockDim.x + threadIdx.x;
    if (e >= E) return;
    int r = ei[e], c = ei[E + e];
    float nrm = -g_dis[r] * ew[e] * g_dis[c];
    int p = atomicAdd(&g_cursor[c], 1);
    g_src[p] = r;
    g_nrm[p] = nrm;
}

// x -> A columns [0,64) hi/lo
__global__ void convert_x_kernel(const float* __restrict__ x, int total) {
    int idx = blockIdx.x * blockDim.x + threadIdx.x;
    if (idx >= total) return;
    int r = idx >> 6, c = idx & 63;
    float v = x[idx];
    __nv_bfloat16 hi = __float2bfloat16_rn(v);
    float lo = v - __bfloat162float(hi);
    g_Ahi[r * KTOT + c] = hi;
    g_Alo[r * KTOT + c] = __float2bfloat16_rn(lo);
}

// warp-per-node gather propagation; fused hi/lo bf16 store into A
__global__ void prop_kernel(const float* __restrict__ xin, int pass, int n) {
    int warp = (blockIdx.x * blockDim.x + threadIdx.x) >> 5;
    int lane = threadIdx.x & 31;
    if (warp >= n) return;
    const float* __restrict__ feat = pass ? g_tx1 : xin;
    int s = g_rowptr[warp], e = g_rowptr[warp + 1];
    float a0 = 0.0f, a1 = 0.0f;
    int p = s;
    for (; p + 1 < e; p += 2) {
        int s0 = __ldg(&g_src[p]);
        int s1 = __ldg(&g_src[p + 1]);
        float w0 = __ldg(&g_nrm[p]);
        float w1 = __ldg(&g_nrm[p + 1]);
        a0 += w0 * __ldg(&feat[s0 * F + lane]);
        a1 += w0 * __ldg(&feat[s0 * F + 32 + lane]);
        a0 += w1 * __ldg(&feat[s1 * F + lane]);
        a1 += w1 * __ldg(&feat[s1 * F + 32 + lane]);
    }
    if (p < e) {
        int s0 = __ldg(&g_src[p]);
        float w0 = __ldg(&g_nrm[p]);
        a0 += w0 * __ldg(&feat[s0 * F + lane]);
        a1 += w0 * __ldg(&feat[s0 * F + 32 + lane]);
    }
    if (pass == 0) {                       // tx1 fp32 needed by pass 1
        g_tx1[warp * F + lane] = a0;
        g_tx1[warp * F + 32 + lane] = a1;
    }
    int cbase = pass ? 128 : 64;
    __nv_bfloat16 h0 = __float2bfloat16_rn(a0);
    __nv_bfloat16 h1 = __float2bfloat16_rn(a1);
    g_Ahi[warp * KTOT + cbase + lane] = h0;
    g_Ahi[warp * KTOT + cbase + 32 + lane] = h1;
    g_Alo[warp * KTOT + cbase + lane] = __float2bfloat16_rn(a0 - __bfloat162float(h0));
    g_Alo[warp * KTOT + cbase + 32 + lane] = __float2bfloat16_rn(a1 - __bfloat162float(h1));
}

// build combined weights -> bf16 hi/lo B stored [n][k] ; biases
__global__ void weights_kernel(const float* __restrict__ Wxz,
                               const float* __restrict__ bxz,
                               const float* __restrict__ bhz,
                               const float* __restrict__ Wxh,
                               const float* __restrict__ bxh,
                               const float* __restrict__ bhh) {
    int idx = blockIdx.x * blockDim.x + threadIdx.x;
    if (idx < KTOT * NOUT) {
        int k = idx / NOUT, nn = idx % NOUT;
        int seg = k / 64, i = k % 64;
        const float* W = (nn < 64) ? Wxz : Wxh;
        int j = (nn < 64) ? nn : (nn - 64);
        float v;
        if (seg == 0)      v = W[(0 * 64 + i) * 64 + j] - W[(2 * 64 + i) * 64 + j];
        else if (seg == 1) v = W[(1 * 64 + i) * 64 + j];
        else               v = 2.0f * W[(2 * 64 + i) * 64 + j];
        __nv_bfloat16 hi = __float2bfloat16_rn(v);
        float lo = v - __bfloat162float(hi);
        g_Bhi[nn * KTOT + k] = hi;
        g_Blo[nn * KTOT + k] = __float2bfloat16_rn(lo);
    }
    if (blockIdx.x == 0 && threadIdx.x < F) {
        g_bz[threadIdx.x] = bxz[threadIdx.x] + bhz[threadIdx.x];
        g_bh[threadIdx.x] = bxh[threadIdx.x] + bhh[threadIdx.x];
    }
}

__device__ __forceinline__ float sigm(float v) { return 1.0f / (1.0f + expf(-v)); }

// ---------------- HMMA bf16x3 GEMM + fused GRU/head epilogue ----------------
// SMEM rows padded to 400B (rotates 16B per row across banks -> conflict-free LDSM)
#define SA_B 400
#define SM_AHI 0
#define SM_ALO 51200
#define SM_BHI 102400
#define SM_BLO 153600
#define GSM_TOTAL 204800
#define SC 132            // C f32 row stride

__global__ __launch_bounds__(256, 1)
void gemm_kernel(const float* __restrict__ Wlin,
                 const float* __restrict__ blin,
                 float* __restrict__ out, int n) {
    extern __shared__ char smem[];
    uint32_t sbase = smem_u32(smem);
    int tid = threadIdx.x, lane = tid & 31, wid = tid >> 5;
    int row0 = blockIdx.x * 128;

    // stage A (hi/lo) and B (hi/lo) into padded SMEM
    for (int it = tid; it < 3072; it += 256) {
        int r = it / 24, c = it % 24;
        int rg = row0 + r;
        uint4 vh = make_uint4(0, 0, 0, 0), vl = make_uint4(0, 0, 0, 0);
        if (rg < n) {
            vh = *reinterpret_cast<const uint4*>(g_Ahi + rg * KTOT + c * 8);
            vl = *reinterpret_cast<const uint4*>(g_Alo + rg * KTOT + c * 8);
        }
        *reinterpret_cast<uint4*>(smem + SM_AHI + r * SA_B + c * 16) = vh;
        *reinterpret_cast<uint4*>(smem + SM_ALO + r * SA_B + c * 16) = vl;
        uint4 bh = *reinterpret_cast<const uint4*>(g_Bhi + r * KTOT + c * 8);
        uint4 bl = *reinterpret_cast<const uint4*>(g_Blo + r * KTOT + c * 8);
        *reinterpret_cast<uint4*>(smem + SM_BHI + r * SA_B + c * 16) = bh;
        *reinterpret_cast<uint4*>(smem + SM_BLO + r * SA_B + c * 16) = bl;
    }
    __syncthreads();

    // warp tiling: 4x2 warps, each 32(M) x 64(N)
    int m0 = (wid & 3) * 32, n0 = (wid >> 2) * 64;
    // ldmatrix per-thread offsets
    int a_r = (lane & 7) + ((lane >> 3) & 1) * 8;   // q0:+0 q1:+8 q2:+0 q3:+8
    int a_k = ((lane >> 4) & 1) * 8;                // q2,q3: k+8
    int b_r = (lane & 7) + ((lane >> 4) & 1) * 8;   // q2,q3: n+8
    int b_k = ((lane >> 3) & 1) * 8;                // q1,q3: k+8

    float acc[2][8][4];
    #pragma unroll
    for (int i = 0; i < 2; i++)
        #pragma unroll
        for (int j = 0; j < 8; j++)
            #pragma unroll
            for (int q = 0; q < 4; q++) acc[i][j][q] = 0.0f;

    #pragma unroll
    for (int pass = 0; pass < 3; pass++) {
        uint32_t abase = sbase + ((pass == 2) ? SM_ALO : SM_AHI);
        uint32_t bbase = sbase + ((pass == 1) ? SM_BLO : SM_BHI);
        uint32_t aaddr0 = abase + (uint32_t)((m0 + a_r) * SA_B + a_k * 2);
        uint32_t aaddr1 = aaddr0 + 16 * SA_B;
        uint32_t baddr0 = bbase + (uint32_t)((n0 + b_r) * SA_B + b_k * 2);
        #pragma unroll
        for (int k = 0; k < KTOT; k += 16) {
            uint32_t a0[4], a1[4], bb[4][4];
            ldsm4(a0, aaddr0 + k * 2);
            ldsm4(a1, aaddr1 + k * 2);
            #pragma unroll
            for (int g = 0; g < 4; g++)
                ldsm4(bb[g], baddr0 + (uint32_t)(g * 16 * SA_B) + k * 2);
            #pragma unroll
            for (int g = 0; g < 4; g++) {
                mma_bf16(acc[0][2 * g],     a0, bb[g][0], bb[g][1]);
                mma_bf16(acc[0][2 * g + 1], a0, bb[g][2], bb[g][3]);
                mma_bf16(acc[1][2 * g],     a1, bb[g][0], bb[g][1]);
                mma_bf16(acc[1][2 * g + 1], a1, bb[g][2], bb[g][3]);
            }
        }
    }
    __syncthreads();

    // write C fragments to SMEM (reuses A region; 128 x 132 f32 = 67.6 KB)
    float* C = reinterpret_cast<float*>(smem);
    #pragma unroll
    for (int ms = 0; ms < 2; ms++) {
        #pragma unroll
        for (int ns = 0; ns < 8; ns++) {
            int r = m0 + ms * 16 + (lane >> 2);
            int c = n0 + ns * 8 + (lane & 3) * 2;
            float2 v0 = make_float2(acc[ms][ns][0], acc[ms][ns][1]);
            float2 v1 = make_float2(acc[ms][ns][2], acc[ms][ns][3]);
            *reinterpret_cast<float2*>(C + r * SC + c) = v0;
            *reinterpret_cast<float2*>(C + (r + 8) * SC + c) = v1;
        }
    }
    __syncthreads();

    // fused epilogue: one thread per row
    if (tid < 128) {
        int r = row0 + tid;
        const float* Cr = C + tid * SC;
        float s0 = 0.0f, s1 = 0.0f;
        #pragma unroll 4
        for (int j = 0; j < 64; j++) {
            float z = sigm(Cr[j] + __ldg(&g_bz[j]));
            float t = tanhf(Cr[j + 64] + __ldg(&g_bh[j]));
            float u = tanhf((1.0f - z) * t);
            s0 += u * __ldg(&Wlin[j * 2 + 0]);
            s1 += u * __ldg(&Wlin[j * 2 + 1]);
        }
        if (r < n) {
            out[r * 2 + 0] = sigm(s0 + __ldg(&blin[0]));
            out[r * 2 + 1] = sigm(s1 + __ldg(&blin[1]));
        }
    }
}

// ---------------- launch ----------------
extern "C" void kernel_launch(void* const* d_in, const int* in_sizes, int n_in,
                              void* d_out, int out_size) {
    const float* x    = (const float*)d_in[0];
    const int*   ei   = (const int*)d_in[1];
    const float* ew   = (const float*)d_in[2];
    const float* Wxz  = (const float*)d_in[3];
    const float* bxz  = (const float*)d_in[4];
    const float* bhz  = (const float*)d_in[6];
    const float* Wxh  = (const float*)d_in[11];
    const float* bxh  = (const float*)d_in[12];
    const float* bhh  = (const float*)d_in[14];
    const float* Wlin = (const float*)d_in[15];
    const float* blin = (const float*)d_in[16];
    float* out = (float*)d_out;

    int n = in_sizes[0] / F;       // 50000
    int E = in_sizes[2];           // 800000
    int nb = (n + SCAN_TILE - 1) / SCAN_TILE;

    cudaFuncSetAttribute(gemm_kernel, cudaFuncAttributeMaxDynamicSharedMemorySize, GSM_TOTAL);

    init_kernel<<<(n + 255) / 256, 256>>>(n);
    edge_pass1_kernel<<<(E + 255) / 256, 256>>>(ei, ew, E);
    dis_kernel<<<(n + 255) / 256, 256>>>(n);
    scan_phase1_kernel<<<nb, SCAN_TILE>>>(n);
    scan_phase2_kernel<<<1, 32>>>(nb, n);
    scan_phase3_kernel<<<(n + 255) / 256, 256>>>(n);
    scatter_kernel<<<(E + 255) / 256, 256>>>(ei, ew, E);

    convert_x_kernel<<<(n * F + 255) / 256, 256>>>(x, n * F);

    int prop_blocks = (n * 32 + 255) / 256;
    prop_kernel<<<prop_blocks, 256>>>(x, 0, n);
    prop_kernel<<<prop_blocks, 256>>>(x, 1, n);

    weights_kernel<<<(KTOT * NOUT + 255) / 256, 256>>>(Wxz, bxz, bhz, Wxh, bxh, bhh);
    gemm_kernel<<<(n + 127) / 128, 256, GSM_TOTAL>>>(Wlin, blin, out, n);
    (void)n_in; (void)out_size;
}

// round 6
// speedup vs baseline: 1.5253x; 1.0327x over previous
#include <cuda_runtime.h>
#include <cuda_bf16.h>
#include <cstdint>
#include <math.h>

#define N_NODES 50000
#define N_EDGES 800000
#define F 64          // F_IN == F_HID
#define KTOT 192      // x | tx1 | y
#define NOUT 128      // z (64) | h (64)
#define SCAN_TILE 1024
#define MAX_BLOCKS ((N_NODES + SCAN_TILE - 1) / SCAN_TILE + 1)

// ---------------- device scratch (allocation-free) ----------------
__device__ float g_deg[N_NODES];
__device__ float g_dis[N_NODES];
__device__ int   g_count[N_NODES];
__device__ int   g_rowptr[N_NODES + 1];
__device__ int   g_cursor[N_NODES];
__device__ int   g_bsum[MAX_BLOCKS];
__device__ int   g_boff[MAX_BLOCKS];
__device__ __align__(16) int2 g_edge[N_EDGES];        // (src, norm-bits)
__device__ __align__(16) float g_tx1[N_NODES * F];
__device__ __align__(16) __nv_bfloat16 g_Ahi[N_NODES * KTOT];
__device__ __align__(16) __nv_bfloat16 g_Alo[N_NODES * KTOT];
__device__ __align__(16) __nv_bfloat16 g_Bhi[NOUT * KTOT];   // [n][k], k-contiguous
__device__ __align__(16) __nv_bfloat16 g_Blo[NOUT * KTOT];
__device__ float g_bz[F];
__device__ float g_bh[F];

// ---------------- PTX helpers ----------------
__device__ __forceinline__ uint32_t smem_u32(const void* p) {
    uint32_t a;
    asm("{ .reg .u64 t; cvta.to.shared.u64 t, %1; cvt.u32.u64 %0, t; }" : "=r"(a) : "l"(p));
    return a;
}
__device__ __forceinline__ void ldsm4(uint32_t (&d)[4], uint32_t addr) {
    asm volatile("ldmatrix.sync.aligned.m8n8.x4.shared.b16 {%0,%1,%2,%3}, [%4];\n"
                 : "=r"(d[0]), "=r"(d[1]), "=r"(d[2]), "=r"(d[3]) : "r"(addr));
}
__device__ __forceinline__ void mma_bf16(float (&c)[4], const uint32_t (&a)[4],
                                         uint32_t b0, uint32_t b1) {
    asm volatile(
        "mma.sync.aligned.m16n8k16.row.col.f32.bf16.bf16.f32 "
        "{%0,%1,%2,%3}, {%4,%5,%6,%7}, {%8,%9}, {%0,%1,%2,%3};\n"
        : "+f"(c[0]), "+f"(c[1]), "+f"(c[2]), "+f"(c[3])
        : "r"(a[0]), "r"(a[1]), "r"(a[2]), "r"(a[3]), "r"(b0), "r"(b1));
}

// ---------------- kernels ----------------

__global__ void init_kernel(int n) {
    int i = blockIdx.x * blockDim.x + threadIdx.x;
    if (i < n) { g_deg[i] = 0.0f; g_count[i] = 0; }
}

__global__ void edge_pass1_kernel(const int* __restrict__ ei,
                                  const float* __restrict__ ew, int E) {
    int e = blockIdx.x * blockDim.x + threadIdx.x;
    if (e >= E) return;
    atomicAdd(&g_deg[ei[e]], ew[e]);
    atomicAdd(&g_count[ei[E + e]], 1);
}

__global__ void scan_phase1_kernel(int n) {
    __shared__ int warp_sums[32];
    int tid = threadIdx.x, lane = tid & 31, wid = tid >> 5;
    int i = blockIdx.x * SCAN_TILE + tid;
    int v = (i < n) ? g_count[i] : 0;
    int incl = v;
    #pragma unroll
    for (int o = 1; o < 32; o <<= 1) {
        int t = __shfl_up_sync(0xffffffffu, incl, o);
        if (lane >= o) incl += t;
    }
    if (lane == 31) warp_sums[wid] = incl;
    __syncthreads();
    if (wid == 0) {
        int s = warp_sums[lane];
        int sincl = s;
        #pragma unroll
        for (int o = 1; o < 32; o <<= 1) {
            int t = __shfl_up_sync(0xffffffffu, sincl, o);
            if (lane >= o) sincl += t;
        }
        warp_sums[lane] = sincl - s;
        if (lane == 31) g_bsum[blockIdx.x] = sincl;
    }
    __syncthreads();
    int excl = warp_sums[wid] + incl - v;
    if (i < n) g_rowptr[i] = excl;
}

__global__ void scan_phase2_kernel(int nb, int n) {
    int lane = threadIdx.x;
    int carry = 0;
    for (int base = 0; base < nb; base += 32) {
        int idx = base + lane;
        int v = (idx < nb) ? g_bsum[idx] : 0;
        int incl = v;
        #pragma unroll
        for (int o = 1; o < 32; o <<= 1) {
            int t = __shfl_up_sync(0xffffffffu, incl, o);
            if (lane >= o) incl += t;
        }
        if (idx < nb) g_boff[idx] = carry + incl - v;
        carry += __shfl_sync(0xffffffffu, incl, 31);
    }
    if (lane == 0) g_rowptr[n] = carry;
}

// phase 3 + dis fused (independent elementwise work, same grid)
__global__ void scan_phase3_kernel(int n) {
    int i = blockIdx.x * blockDim.x + threadIdx.x;
    if (i >= n) return;
    int val = g_rowptr[i] + g_boff[i >> 10];
    g_rowptr[i] = val;
    g_cursor[i] = val;
    float d = g_deg[i];
    g_dis[i] = (d > 0.0f) ? rsqrtf(d) : 0.0f;
}

__global__ void scatter_kernel(const int* __restrict__ ei,
                               const float* __restrict__ ew, int E) {
    int e = blockIdx.x * blockDim.x + threadIdx.x;
    if (e >= E) return;
    int r = ei[e], c = ei[E + e];
    float nrm = -g_dis[r] * ew[e] * g_dis[c];
    int p = atomicAdd(&g_cursor[c], 1);
    g_edge[p] = make_int2(r, __float_as_int(nrm));
}

// x -> A columns [0,64) hi/lo (float2 in, bf162 out)
__global__ void convert_x_kernel(const float* __restrict__ x, int total2) {
    int idx = blockIdx.x * blockDim.x + threadIdx.x;
    if (idx >= total2) return;
    int r = idx >> 5, l = idx & 31;
    float2 v = reinterpret_cast<const float2*>(x)[idx];
    __nv_bfloat16 h0 = __float2bfloat16_rn(v.x);
    __nv_bfloat16 h1 = __float2bfloat16_rn(v.y);
    __nv_bfloat162 hi; hi.x = h0; hi.y = h1;
    __nv_bfloat162 lo;
    lo.x = __float2bfloat16_rn(v.x - __bfloat162float(h0));
    lo.y = __float2bfloat16_rn(v.y - __bfloat162float(h1));
    *reinterpret_cast<__nv_bfloat162*>(g_Ahi + r * KTOT + 2 * l) = hi;
    *reinterpret_cast<__nv_bfloat162*>(g_Alo + r * KTOT + 2 * l) = lo;
}

// warp-per-node gather propagation; float2 features, int2 edge meta, unroll 4
__global__ void prop_kernel(const float* __restrict__ xin, int pass, int n) {
    int warp = (blockIdx.x * blockDim.x + threadIdx.x) >> 5;
    int lane = threadIdx.x & 31;
    if (warp >= n) return;
    const float2* __restrict__ feat =
        reinterpret_cast<const float2*>(pass ? g_tx1 : xin);
    int s = g_rowptr[warp], e = g_rowptr[warp + 1];
    float a0 = 0.0f, a1 = 0.0f;
    int p = s;
    for (; p + 3 < e; p += 4) {
        int2 e0 = __ldg(&g_edge[p]);
        int2 e1 = __ldg(&g_edge[p + 1]);
        int2 e2 = __ldg(&g_edge[p + 2]);
        int2 e3 = __ldg(&g_edge[p + 3]);
        float2 f0 = __ldg(&feat[e0.x * 32 + lane]);
        float2 f1 = __ldg(&feat[e1.x * 32 + lane]);
        float2 f2 = __ldg(&feat[e2.x * 32 + lane]);
        float2 f3 = __ldg(&feat[e3.x * 32 + lane]);
        float w0 = __int_as_float(e0.y), w1 = __int_as_float(e1.y);
        float w2 = __int_as_float(e2.y), w3 = __int_as_float(e3.y);
        a0 += w0 * f0.x; a1 += w0 * f0.y;
        a0 += w1 * f1.x; a1 += w1 * f1.y;
        a0 += w2 * f2.x; a1 += w2 * f2.y;
        a0 += w3 * f3.x; a1 += w3 * f3.y;
    }
    for (; p < e; p++) {
        int2 e0 = __ldg(&g_edge[p]);
        float2 f0 = __ldg(&feat[e0.x * 32 + lane]);
        float w0 = __int_as_float(e0.y);
        a0 += w0 * f0.x; a1 += w0 * f0.y;
    }
    if (pass == 0) {   // tx1 fp32 needed by pass 1 (same float2 layout)
        reinterpret_cast<float2*>(g_tx1)[warp * 32 + lane] = make_float2(a0, a1);
    }
    int cbase = pass ? 128 : 64;
    __nv_bfloat16 h0 = __float2bfloat16_rn(a0);
    __nv_bfloat16 h1 = __float2bfloat16_rn(a1);
    __nv_bfloat162 hi; hi.x = h0; hi.y = h1;
    __nv_bfloat162 lo;
    lo.x = __float2bfloat16_rn(a0 - __bfloat162float(h0));
    lo.y = __float2bfloat16_rn(a1 - __bfloat162float(h1));
    *reinterpret_cast<__nv_bfloat162*>(g_Ahi + warp * KTOT + cbase + 2 * lane) = hi;
    *reinterpret_cast<__nv_bfloat162*>(g_Alo + warp * KTOT + cbase + 2 * lane) = lo;
}

// build combined weights -> bf16 hi/lo B stored [n][k] ; biases
__global__ void weights_kernel(const float* __restrict__ Wxz,
                               const float* __restrict__ bxz,
                               const float* __restrict__ bhz,
                               const float* __restrict__ Wxh,
                               const float* __restrict__ bxh,
                               const float* __restrict__ bhh) {
    int idx = blockIdx.x * blockDim.x + threadIdx.x;
    if (idx < KTOT * NOUT) {
        int k = idx / NOUT, nn = idx % NOUT;
        int seg = k / 64, i = k % 64;
        const float* W = (nn < 64) ? Wxz : Wxh;
        int j = (nn < 64) ? nn : (nn - 64);
        float v;
        if (seg == 0)      v = W[(0 * 64 + i) * 64 + j] - W[(2 * 64 + i) * 64 + j];
        else if (seg == 1) v = W[(1 * 64 + i) * 64 + j];
        else               v = 2.0f * W[(2 * 64 + i) * 64 + j];
        __nv_bfloat16 hi = __float2bfloat16_rn(v);
        float lo = v - __bfloat162float(hi);
        g_Bhi[nn * KTOT + k] = hi;
        g_Blo[nn * KTOT + k] = __float2bfloat16_rn(lo);
    }
    if (blockIdx.x == 0 && threadIdx.x < F) {
        g_bz[threadIdx.x] = bxz[threadIdx.x] + bhz[threadIdx.x];
        g_bh[threadIdx.x] = bxh[threadIdx.x] + bhh[threadIdx.x];
    }
}

__device__ __forceinline__ float sigm(float v) { return 1.0f / (1.0f + expf(-v)); }

// ---------------- HMMA bf16x3 GEMM + fused GRU/head epilogue ----------------
// SMEM rows padded to 400B (rotates 16B per row across banks -> conflict-free LDSM)
#define SA_B 400
#define SM_AHI 0
#define SM_ALO 51200
#define SM_BHI 102400
#define SM_BLO 153600
#define GSM_TOTAL 204800
#define SC 132            // C f32 row stride

__global__ __launch_bounds__(256, 1)
void gemm_kernel(const float* __restrict__ Wlin,
                 const float* __restrict__ blin,
                 float* __restrict__ out, int n) {
    extern __shared__ char smem[];
    uint32_t sbase = smem_u32(smem);
    int tid = threadIdx.x, lane = tid & 31, wid = tid >> 5;
    int row0 = blockIdx.x * 128;

    // stage A (hi/lo) and B (hi/lo) into padded SMEM
    for (int it = tid; it < 3072; it += 256) {
        int r = it / 24, c = it % 24;
        int rg = row0 + r;
        uint4 vh = make_uint4(0, 0, 0, 0), vl = make_uint4(0, 0, 0, 0);
        if (rg < n) {
            vh = *reinterpret_cast<const uint4*>(g_Ahi + rg * KTOT + c * 8);
            vl = *reinterpret_cast<const uint4*>(g_Alo + rg * KTOT + c * 8);
        }
        *reinterpret_cast<uint4*>(smem + SM_AHI + r * SA_B + c * 16) = vh;
        *reinterpret_cast<uint4*>(smem + SM_ALO + r * SA_B + c * 16) = vl;
        uint4 bh = *reinterpret_cast<const uint4*>(g_Bhi + r * KTOT + c * 8);
        uint4 bl = *reinterpret_cast<const uint4*>(g_Blo + r * KTOT + c * 8);
        *reinterpret_cast<uint4*>(smem + SM_BHI + r * SA_B + c * 16) = bh;
        *reinterpret_cast<uint4*>(smem + SM_BLO + r * SA_B + c * 16) = bl;
    }
    __syncthreads();

    // warp tiling: 4x2 warps, each 32(M) x 64(N)
    int m0 = (wid & 3) * 32, n0 = (wid >> 2) * 64;
    // ldmatrix per-thread offsets
    int a_r = (lane & 7) + ((lane >> 3) & 1) * 8;
    int a_k = ((lane >> 4) & 1) * 8;
    int b_r = (lane & 7) + ((lane >> 4) & 1) * 8;
    int b_k = ((lane >> 3) & 1) * 8;

    float acc[2][8][4];
    #pragma unroll
    for (int i = 0; i < 2; i++)
        #pragma unroll
        for (int j = 0; j < 8; j++)
            #pragma unroll
            for (int q = 0; q < 4; q++) acc[i][j][q] = 0.0f;

    #pragma unroll
    for (int pass = 0; pass < 3; pass++) {
        uint32_t abase = sbase + ((pass == 2) ? SM_ALO : SM_AHI);
        uint32_t bbase = sbase + ((pass == 1) ? SM_BLO : SM_BHI);
        uint32_t aaddr0 = abase + (uint32_t)((m0 + a_r) * SA_B + a_k * 2);
        uint32_t aaddr1 = aaddr0 + 16 * SA_B;
        uint32_t baddr0 = bbase + (uint32_t)((n0 + b_r) * SA_B + b_k * 2);
        #pragma unroll
        for (int k = 0; k < KTOT; k += 16) {
            uint32_t a0[4], a1[4], bb[4][4];
            ldsm4(a0, aaddr0 + k * 2);
            ldsm4(a1, aaddr1 + k * 2);
            #pragma unroll
            for (int g = 0; g < 4; g++)
                ldsm4(bb[g], baddr0 + (uint32_t)(g * 16 * SA_B) + k * 2);
            #pragma unroll
            for (int g = 0; g < 4; g++) {
                mma_bf16(acc[0][2 * g],     a0, bb[g][0], bb[g][1]);
                mma_bf16(acc[0][2 * g + 1], a0, bb[g][2], bb[g][3]);
                mma_bf16(acc[1][2 * g],     a1, bb[g][0], bb[g][1]);
                mma_bf16(acc[1][2 * g + 1], a1, bb[g][2], bb[g][3]);
            }
        }
    }
    __syncthreads();

    // write C fragments to SMEM (reuses A region; 128 x 132 f32 = 67.6 KB)
    float* C = reinterpret_cast<float*>(smem);
    #pragma unroll
    for (int ms = 0; ms < 2; ms++) {
        #pragma unroll
        for (int ns = 0; ns < 8; ns++) {
            int r = m0 + ms * 16 + (lane >> 2);
            int c = n0 + ns * 8 + (lane & 3) * 2;
            float2 v0 = make_float2(acc[ms][ns][0], acc[ms][ns][1]);
            float2 v1 = make_float2(acc[ms][ns][2], acc[ms][ns][3]);
            *reinterpret_cast<float2*>(C + r * SC + c) = v0;
            *reinterpret_cast<float2*>(C + (r + 8) * SC + c) = v1;
        }
    }
    __syncthreads();

    // fused epilogue: one thread per row
    if (tid < 128) {
        int r = row0 + tid;
        const float* Cr = C + tid * SC;
        float s0 = 0.0f, s1 = 0.0f;
        #pragma unroll 4
        for (int j = 0; j < 64; j++) {
            float z = sigm(Cr[j] + __ldg(&g_bz[j]));
            float t = tanhf(Cr[j + 64] + __ldg(&g_bh[j]));
            float u = tanhf((1.0f - z) * t);
            s0 += u * __ldg(&Wlin[j * 2 + 0]);
            s1 += u * __ldg(&Wlin[j * 2 + 1]);
        }
        if (r < n) {
            out[r * 2 + 0] = sigm(s0 + __ldg(&blin[0]));
            out[r * 2 + 1] = sigm(s1 + __ldg(&blin[1]));
        }
    }
}

// ---------------- launch ----------------
extern "C" void kernel_launch(void* const* d_in, const int* in_sizes, int n_in,
                              void* d_out, int out_size) {
    const float* x    = (const float*)d_in[0];
    const int*   ei   = (const int*)d_in[1];
    const float* ew   = (const float*)d_in[2];
    const float* Wxz  = (const float*)d_in[3];
    const float* bxz  = (const float*)d_in[4];
    const float* bhz  = (const float*)d_in[6];
    const float* Wxh  = (const float*)d_in[11];
    const float* bxh  = (const float*)d_in[12];
    const float* bhh  = (const float*)d_in[14];
    const float* Wlin = (const float*)d_in[15];
    const float* blin = (const float*)d_in[16];
    float* out = (float*)d_out;

    int n = in_sizes[0] / F;       // 50000
    int E = in_sizes[2];           // 800000
    int nb = (n + SCAN_TILE - 1) / SCAN_TILE;

    cudaFuncSetAttribute(gemm_kernel, cudaFuncAttributeMaxDynamicSharedMemorySize, GSM_TOTAL);

    init_kernel<<<(n + 255) / 256, 256>>>(n);
    edge_pass1_kernel<<<(E + 255) / 256, 256>>>(ei, ew, E);
    scan_phase1_kernel<<<nb, SCAN_TILE>>>(n);
    scan_phase2_kernel<<<1, 32>>>(nb, n);
    scan_phase3_kernel<<<(n + 255) / 256, 256>>>(n);   // + dis fused
    scatter_kernel<<<(E + 255) / 256, 256>>>(ei, ew, E);

    convert_x_kernel<<<(n * 32 + 255) / 256, 256>>>(x, n * 32);

    int prop_blocks = (n * 32 + 255) / 256;
    prop_kernel<<<prop_blocks, 256>>>(x, 0, n);
    prop_kernel<<<prop_blocks, 256>>>(x, 1, n);

    weights_kernel<<<(KTOT * NOUT + 255) / 256, 256>>>(Wxz, bxz, bhz, Wxh, bxh, bhh);
    gemm_kernel<<<(n + 127) / 128, 256, GSM_TOTAL>>>(Wlin, blin, out, n);
    (void)n_in; (void)out_size;
}